// round 2
// baseline (speedup 1.0000x reference)
#include <cuda_runtime.h>

#define NTOK 4096
#define CDIM 256
#define FDIM 64
#define BATCH 8

// Scratch (allocation-free rule: __device__ globals)
__device__ float g_f[BATCH * NTOK * FDIM];   // 8 MB
__device__ float g_g[BATCH * NTOK * FDIM];   // 8 MB
__device__ float g_h[BATCH * NTOK * CDIM];   // 32 MB
__device__ float g_o[BATCH * NTOK * CDIM];   // 32 MB

// ---------------------------------------------------------------------------
// Generic 64x64-tile GEMM: C[M,N] = A[M,K] @ W[K,N]
// MODE 0/1/2: C = g_f / g_g / g_h.  MODE 3: A = g_o, C = out, epilogue
//             C = gamma*acc + X (residual).
// 256 threads, 4x4 micro-tile per thread, BK=16.
// ---------------------------------------------------------------------------
template <int MODE>
__global__ __launch_bounds__(256) void gemm_k(
    const float* __restrict__ Aext, const float* __restrict__ W,
    float* __restrict__ Cext, const float* __restrict__ X,
    const float* __restrict__ gamma, int M, int K, int N)
{
    __shared__ float As[64][17];   // pad 17: scalar reads 2-way max
    __shared__ float Ws[16][64];

    const float* __restrict__ A = (MODE == 3) ? g_o : Aext;
    float* __restrict__ C =
        (MODE == 0) ? g_f : (MODE == 1) ? g_g : (MODE == 2) ? g_h : Cext;

    const int m0 = blockIdx.x * 64;
    const int n0 = blockIdx.y * 64;
    const int tid = threadIdx.x;
    const int ty = tid >> 4;       // 0..15 row group
    const int tx = tid & 15;       // 0..15 col group

    float acc[4][4];
#pragma unroll
    for (int i = 0; i < 4; i++)
#pragma unroll
        for (int j = 0; j < 4; j++) acc[i][j] = 0.0f;

    for (int k0 = 0; k0 < K; k0 += 16) {
        {
            int r = tid >> 2;
            int q = (tid & 3) << 2;
            float4 v = *(const float4*)(A + (size_t)(m0 + r) * K + k0 + q);
            As[r][q + 0] = v.x; As[r][q + 1] = v.y;
            As[r][q + 2] = v.z; As[r][q + 3] = v.w;
        }
        {
            int kr = tid >> 4;
            int cq = (tid & 15) << 2;
            *(float4*)(&Ws[kr][cq]) =
                *(const float4*)(W + (size_t)(k0 + kr) * N + n0 + cq);
        }
        __syncthreads();
#pragma unroll
        for (int k = 0; k < 16; k++) {
            float4 b = *(const float4*)(&Ws[k][tx << 2]);
#pragma unroll
            for (int i = 0; i < 4; i++) {
                float a = As[(ty << 2) + i][k];
                acc[i][0] += a * b.x; acc[i][1] += a * b.y;
                acc[i][2] += a * b.z; acc[i][3] += a * b.w;
            }
        }
        __syncthreads();
    }

    float gam = (MODE == 3) ? *gamma : 0.0f;
#pragma unroll
    for (int i = 0; i < 4; i++) {
        size_t row = (size_t)(m0 + (ty << 2) + i);
        float4 v;
        if (MODE == 3) {
            float4 xr = *(const float4*)(X + row * N + n0 + (tx << 2));
            v.x = gam * acc[i][0] + xr.x;
            v.y = gam * acc[i][1] + xr.y;
            v.z = gam * acc[i][2] + xr.z;
            v.w = gam * acc[i][3] + xr.w;
        } else {
            v.x = acc[i][0]; v.y = acc[i][1]; v.z = acc[i][2]; v.w = acc[i][3];
        }
        *(float4*)(C + row * N + n0 + (tx << 2)) = v;
    }
}

// ---------------------------------------------------------------------------
// Flash attention: per CTA one (batch, 64-row i-tile). Streams 64-row j-tiles.
// Thread layout: rg = tid>>4 owns rows rg*4..rg*4+3;
//                cg = tid&15 owns S-cols {cg+16j} and V-channels cg*16..+15.
// ---------------------------------------------------------------------------
struct AttnSmem {
    float fs[64][64];    // f i-tile            16 KB
    float gs[64][68];    // g j-tile (padded)   17 KB
    float hs[64][256];   // h j-tile            64 KB
    float ps[64][64];    // P tile              16 KB
    float redm[16][64];  // row reductions       4 KB
};

__global__ __launch_bounds__(256) void attn_k() {
    extern __shared__ char sraw[];
    AttnSmem& sm = *reinterpret_cast<AttnSmem*>(sraw);

    const int b  = blockIdx.y;
    const int i0 = blockIdx.x * 64;
    const int tid = threadIdx.x;
    const int rg = tid >> 4;
    const int cg = tid & 15;
    const int r0 = rg << 2;

    const float* __restrict__ fb = g_f + (size_t)b * NTOK * FDIM;
    const float* __restrict__ gb = g_g + (size_t)b * NTOK * FDIM;
    const float* __restrict__ hb = g_h + (size_t)b * NTOK * CDIM;

    // load f i-tile once
    for (int idx = tid; idx < 64 * 16; idx += 256) {
        int r = idx >> 4, c = (idx & 15) << 2;
        *(float4*)&sm.fs[r][c] = *(const float4*)(fb + (size_t)(i0 + r) * FDIM + c);
    }

    float4 acc[4][4];
#pragma unroll
    for (int i = 0; i < 4; i++)
#pragma unroll
        for (int q = 0; q < 4; q++) acc[i][q] = make_float4(0.f, 0.f, 0.f, 0.f);
    float m[4] = {-1e30f, -1e30f, -1e30f, -1e30f};
    float l[4] = {0.f, 0.f, 0.f, 0.f};

    for (int j0 = 0; j0 < NTOK; j0 += 64) {
        __syncthreads();  // prior tile's smem reads complete
        for (int idx = tid; idx < 64 * 16; idx += 256) {
            int r = idx >> 4, c = (idx & 15) << 2;
            *(float4*)&sm.gs[r][c] =
                *(const float4*)(gb + (size_t)(j0 + r) * FDIM + c);
        }
        for (int idx = tid; idx < 64 * 64; idx += 256) {
            int r = idx >> 6, c = (idx & 63) << 2;
            *(float4*)&sm.hs[r][c] =
                *(const float4*)(hb + (size_t)(j0 + r) * CDIM + c);
        }
        __syncthreads();

        // S = f_i @ g_j^T   (thread: 4 rows x cols {cg+16j})
        float s[4][4];
#pragma unroll
        for (int i = 0; i < 4; i++)
#pragma unroll
            for (int j = 0; j < 4; j++) s[i][j] = 0.f;

#pragma unroll 4
        for (int kk = 0; kk < 64; kk += 4) {
            float4 av[4], bv[4];
#pragma unroll
            for (int i = 0; i < 4; i++)
                av[i] = *(const float4*)&sm.fs[r0 + i][kk];
#pragma unroll
            for (int j = 0; j < 4; j++)
                bv[j] = *(const float4*)&sm.gs[cg + (j << 4)][kk];
#pragma unroll
            for (int i = 0; i < 4; i++)
#pragma unroll
                for (int j = 0; j < 4; j++) {
                    s[i][j] += av[i].x * bv[j].x;
                    s[i][j] += av[i].y * bv[j].y;
                    s[i][j] += av[i].z * bv[j].z;
                    s[i][j] += av[i].w * bv[j].w;
                }
        }

        // tile row-max -> smem reduction
#pragma unroll
        for (int i = 0; i < 4; i++) {
            float tm = fmaxf(fmaxf(s[i][0], s[i][1]), fmaxf(s[i][2], s[i][3]));
            sm.redm[cg][r0 + i] = tm;
        }
        __syncthreads();

        float alpha[4];
#pragma unroll
        for (int i = 0; i < 4; i++) {
            float mx = sm.redm[0][r0 + i];
#pragma unroll
            for (int c2 = 1; c2 < 16; c2++)
                mx = fmaxf(mx, sm.redm[c2][r0 + i]);
            float nm = fmaxf(m[i], mx);
            alpha[i] = __expf(m[i] - nm);
            m[i] = nm;
        }

        // P = exp(S - m), partial row-sums kept per-thread (linear in rescale)
#pragma unroll
        for (int i = 0; i < 4; i++) {
            float tl = 0.f;
#pragma unroll
            for (int j = 0; j < 4; j++) {
                float p = __expf(s[i][j] - m[i]);
                sm.ps[r0 + i][cg + (j << 4)] = p;
                tl += p;
            }
            l[i] = l[i] * alpha[i] + tl;
        }
        __syncthreads();

        // rescale accumulators
#pragma unroll
        for (int i = 0; i < 4; i++) {
            float a = alpha[i];
#pragma unroll
            for (int q = 0; q < 4; q++) {
                acc[i][q].x *= a; acc[i][q].y *= a;
                acc[i][q].z *= a; acc[i][q].w *= a;
            }
        }

        // acc += P @ h_j   (thread: 4 rows x 16 channels at cg*16)
#pragma unroll 1
        for (int j4 = 0; j4 < 64; j4 += 4) {
            float4 pr[4];
#pragma unroll
            for (int i = 0; i < 4; i++)
                pr[i] = *(const float4*)&sm.ps[r0 + i][j4];
#pragma unroll
            for (int jj = 0; jj < 4; jj++) {
                float4 hv[4];
#pragma unroll
                for (int q = 0; q < 4; q++)
                    hv[q] = *(const float4*)&sm.hs[j4 + jj][(cg << 4) + (q << 2)];
                float pj[4];
                pj[0] = (jj == 0) ? pr[0].x : (jj == 1) ? pr[0].y : (jj == 2) ? pr[0].z : pr[0].w;
                pj[1] = (jj == 0) ? pr[1].x : (jj == 1) ? pr[1].y : (jj == 2) ? pr[1].z : pr[1].w;
                pj[2] = (jj == 0) ? pr[2].x : (jj == 1) ? pr[2].y : (jj == 2) ? pr[2].z : pr[2].w;
                pj[3] = (jj == 0) ? pr[3].x : (jj == 1) ? pr[3].y : (jj == 2) ? pr[3].z : pr[3].w;
#pragma unroll
                for (int i = 0; i < 4; i++)
#pragma unroll
                    for (int q = 0; q < 4; q++) {
                        acc[i][q].x += pj[i] * hv[q].x;
                        acc[i][q].y += pj[i] * hv[q].y;
                        acc[i][q].z += pj[i] * hv[q].z;
                        acc[i][q].w += pj[i] * hv[q].w;
                    }
            }
        }
    }

    // final l reduction (reuse redm) and write o
    __syncthreads();
#pragma unroll
    for (int i = 0; i < 4; i++) sm.redm[cg][r0 + i] = l[i];
    __syncthreads();
#pragma unroll
    for (int i = 0; i < 4; i++) {
        float ls = 0.f;
#pragma unroll
        for (int c2 = 0; c2 < 16; c2++) ls += sm.redm[c2][r0 + i];
        float inv = 1.0f / ls;
        float* op = g_o + ((size_t)b * NTOK + i0 + r0 + i) * CDIM + (cg << 4);
#pragma unroll
        for (int q = 0; q < 4; q++) {
            float4 v = acc[i][q];
            v.x *= inv; v.y *= inv; v.z *= inv; v.w *= inv;
            *(float4*)(op + (q << 2)) = v;
        }
    }
}

// ---------------------------------------------------------------------------
extern "C" void kernel_launch(void* const* d_in, const int* in_sizes, int n_in,
                              void* d_out, int out_size) {
    const float* x     = (const float*)d_in[0];   // [8,64,64,256]
    const float* Wf    = (const float*)d_in[1];   // [1,1,256,64]
    const float* Wg    = (const float*)d_in[2];   // [1,1,256,64]
    const float* Wh    = (const float*)d_in[3];   // [1,1,256,256]
    const float* Wv    = (const float*)d_in[4];   // [1,1,256,256]
    const float* gamma = (const float*)d_in[5];   // [1]
    float* out = (float*)d_out;

    const int M = BATCH * NTOK;  // 32768

    // projections
    gemm_k<0><<<dim3(M / 64, 1), 256>>>(x, Wf, nullptr, nullptr, nullptr, M, CDIM, FDIM);
    gemm_k<1><<<dim3(M / 64, 1), 256>>>(x, Wg, nullptr, nullptr, nullptr, M, CDIM, FDIM);
    gemm_k<2><<<dim3(M / 64, 4), 256>>>(x, Wh, nullptr, nullptr, nullptr, M, CDIM, CDIM);

    // fused attention
    static_assert(sizeof(AttnSmem) <= 128 * 1024, "smem");
    cudaFuncSetAttribute(attn_k, cudaFuncAttributeMaxDynamicSharedMemorySize,
                         (int)sizeof(AttnSmem));
    attn_k<<<dim3(NTOK / 64, BATCH), 256, sizeof(AttnSmem)>>>();

    // out = gamma*(o @ Wv) + x
    gemm_k<3><<<dim3(M / 64, 4), 256>>>(nullptr, Wv, out, x, gamma, M, CDIM, CDIM);
}

// round 4
// speedup vs baseline: 3.5106x; 3.5106x over previous
#include <cuda_runtime.h>
#include <cstdint>

#define NTOK 4096
#define CDIM 256
#define FDIM 64
#define BATCH 8

// Scratch (allocation-free rule: __device__ globals)
__device__ float g_f[BATCH * NTOK * FDIM];   // 8 MB
__device__ float g_g[BATCH * NTOK * FDIM];   // 8 MB
__device__ float g_h[BATCH * NTOK * CDIM];   // 32 MB
__device__ float g_o[BATCH * NTOK * CDIM];   // 32 MB

// ---------------------------------------------------------------------------
// helpers
// ---------------------------------------------------------------------------
__device__ __forceinline__ float to_tf32(float x) {
    unsigned int u;
    asm("cvt.rna.tf32.f32 %0, %1;" : "=r"(u) : "f"(x));
    return __uint_as_float(u);
}

__device__ __forceinline__ void mma_tf32(float c[4], const float a[4],
                                         float b0, float b1) {
    asm volatile(
        "mma.sync.aligned.m16n8k8.row.col.f32.tf32.tf32.f32 "
        "{%0,%1,%2,%3}, {%4,%5,%6,%7}, {%8,%9}, {%0,%1,%2,%3};"
        : "+f"(c[0]), "+f"(c[1]), "+f"(c[2]), "+f"(c[3])
        : "r"(__float_as_uint(a[0])), "r"(__float_as_uint(a[1])),
          "r"(__float_as_uint(a[2])), "r"(__float_as_uint(a[3])),
          "r"(__float_as_uint(b0)), "r"(__float_as_uint(b1)));
}

// ---------------------------------------------------------------------------
// Generic 64x64-tile GEMM: C[M,N] = A[M,K] @ W[K,N]
// MODE 0/1/2: C = g_f / g_g / g_h.  MODE 3: A = g_o, C = out, epilogue
//             C = gamma*acc + X (residual).
// ---------------------------------------------------------------------------
template <int MODE>
__global__ __launch_bounds__(256) void gemm_k(
    const float* __restrict__ Aext, const float* __restrict__ W,
    float* __restrict__ Cext, const float* __restrict__ X,
    const float* __restrict__ gamma, int M, int K, int N)
{
    __shared__ float As[64][17];
    __shared__ float Ws[16][64];

    const float* __restrict__ A = (MODE == 3) ? g_o : Aext;
    float* __restrict__ C =
        (MODE == 0) ? g_f : (MODE == 1) ? g_g : (MODE == 2) ? g_h : Cext;

    const int m0 = blockIdx.x * 64;
    const int n0 = blockIdx.y * 64;
    const int tid = threadIdx.x;
    const int ty = tid >> 4;
    const int tx = tid & 15;

    float acc[4][4];
#pragma unroll
    for (int i = 0; i < 4; i++)
#pragma unroll
        for (int j = 0; j < 4; j++) acc[i][j] = 0.0f;

    for (int k0 = 0; k0 < K; k0 += 16) {
        {
            int r = tid >> 2;
            int q = (tid & 3) << 2;
            float4 v = *(const float4*)(A + (size_t)(m0 + r) * K + k0 + q);
            As[r][q + 0] = v.x; As[r][q + 1] = v.y;
            As[r][q + 2] = v.z; As[r][q + 3] = v.w;
        }
        {
            int kr = tid >> 4;
            int cq = (tid & 15) << 2;
            *(float4*)(&Ws[kr][cq]) =
                *(const float4*)(W + (size_t)(k0 + kr) * N + n0 + cq);
        }
        __syncthreads();
#pragma unroll
        for (int k = 0; k < 16; k++) {
            float4 b = *(const float4*)(&Ws[k][tx << 2]);
#pragma unroll
            for (int i = 0; i < 4; i++) {
                float a = As[(ty << 2) + i][k];
                acc[i][0] += a * b.x; acc[i][1] += a * b.y;
                acc[i][2] += a * b.z; acc[i][3] += a * b.w;
            }
        }
        __syncthreads();
    }

    float gam = (MODE == 3) ? *gamma : 0.0f;
#pragma unroll
    for (int i = 0; i < 4; i++) {
        size_t row = (size_t)(m0 + (ty << 2) + i);
        float4 v;
        if (MODE == 3) {
            float4 xr = *(const float4*)(X + row * N + n0 + (tx << 2));
            v.x = gam * acc[i][0] + xr.x;
            v.y = gam * acc[i][1] + xr.y;
            v.z = gam * acc[i][2] + xr.z;
            v.w = gam * acc[i][3] + xr.w;
        } else {
            v.x = acc[i][0]; v.y = acc[i][1]; v.z = acc[i][2]; v.w = acc[i][3];
        }
        *(float4*)(C + row * N + n0 + (tx << 2)) = v;
    }
}

// ---------------------------------------------------------------------------
// Flash attention with tf32 mma.sync (m16n8k8).
// CTA = 256 threads = 8 warps: rw = wid&1 (row half: 32 rows each),
// cw = wid>>1 (4 groups: 16 j-cols in S phase, 64 channels in PV phase).
// i-tile = 64 rows, j-tile = 64. All smem tiles pre-converted to tf32.
// ---------------------------------------------------------------------------
struct AttnSmem {
    float gs[64][68];    // g j-tile (tf32)    17408 B
    float hs[64][264];   // h j-tile (tf32)    67584 B
    float ps[64][68];    // P tile  (tf32)     17408 B
    float redm[4][64];   // per-cw row max       1024 B
    float reds[4][64];   // per-cw row sums      1024 B
};

__global__ __launch_bounds__(256) void attn_k() {
    extern __shared__ char sraw[];
    AttnSmem& sm = *reinterpret_cast<AttnSmem*>(sraw);

    const int tid  = threadIdx.x;
    const int wid  = tid >> 5;
    const int lane = tid & 31;
    const int g    = lane >> 2;     // 0..7
    const int tg   = lane & 3;      // 0..3
    const int rw   = wid & 1;
    const int cw   = wid >> 1;      // 0..3
    const int rb   = rw << 5;       // 0 / 32

    const int b  = blockIdx.y;
    const int i0 = blockIdx.x * 64;

    const float* __restrict__ fb = g_f + (size_t)b * NTOK * FDIM;
    const float* __restrict__ gb = g_g + (size_t)b * NTOK * FDIM;
    const float* __restrict__ hb = g_h + (size_t)b * NTOK * CDIM;

    // persistent A fragments of f (tf32), 2 m16 blocks x 8 k-blocks
    float aS[2][8][4];
#pragma unroll
    for (int mi = 0; mi < 2; mi++) {
        int row0 = i0 + rb + mi * 16 + g;
#pragma unroll
        for (int kb = 0; kb < 8; kb++) {
            int k0 = kb * 8 + tg;
            aS[mi][kb][0] = to_tf32(fb[(size_t)row0 * FDIM + k0]);
            aS[mi][kb][1] = to_tf32(fb[(size_t)(row0 + 8) * FDIM + k0]);
            aS[mi][kb][2] = to_tf32(fb[(size_t)row0 * FDIM + k0 + 4]);
            aS[mi][kb][3] = to_tf32(fb[(size_t)(row0 + 8) * FDIM + k0 + 4]);
        }
    }

    float acc[2][8][4];
#pragma unroll
    for (int mi = 0; mi < 2; mi++)
#pragma unroll
        for (int nb = 0; nb < 8; nb++)
#pragma unroll
            for (int q = 0; q < 4; q++) acc[mi][nb][q] = 0.0f;

    float m[2][2] = {{-1e30f, -1e30f}, {-1e30f, -1e30f}};
    float l[2][2] = {{0.f, 0.f}, {0.f, 0.f}};

    for (int j0 = 0; j0 < NTOK; j0 += 64) {
        __syncthreads();  // protect gs/hs/ps reuse
        // cooperative loads with tf32 conversion
        for (int idx = tid; idx < 64 * 16; idx += 256) {
            int r = idx >> 4, c = (idx & 15) << 2;
            float4 v = *(const float4*)(gb + (size_t)(j0 + r) * FDIM + c);
            float4 w = make_float4(to_tf32(v.x), to_tf32(v.y),
                                   to_tf32(v.z), to_tf32(v.w));
            *(float4*)&sm.gs[r][c] = w;
        }
        for (int idx = tid; idx < 64 * 64; idx += 256) {
            int r = idx >> 6, c = (idx & 63) << 2;
            float4 v = *(const float4*)(hb + (size_t)(j0 + r) * CDIM + c);
            float4 w = make_float4(to_tf32(v.x), to_tf32(v.y),
                                   to_tf32(v.z), to_tf32(v.w));
            *(float4*)&sm.hs[r][c] = w;
        }
        __syncthreads();

        // ---- S = f_i @ g_j^T : warp covers 32 rows x 16 j-cols ----
        float sc[2][2][4];
#pragma unroll
        for (int mi = 0; mi < 2; mi++)
#pragma unroll
            for (int nb = 0; nb < 2; nb++)
#pragma unroll
                for (int q = 0; q < 4; q++) sc[mi][nb][q] = 0.f;

#pragma unroll
        for (int kb = 0; kb < 8; kb++) {
#pragma unroll
            for (int nb = 0; nb < 2; nb++) {
                int jn = (cw << 4) + nb * 8 + g;
                float b0 = sm.gs[jn][kb * 8 + tg];
                float b1 = sm.gs[jn][kb * 8 + tg + 4];
#pragma unroll
                for (int mi = 0; mi < 2; mi++)
                    mma_tf32(sc[mi][nb], aS[mi][kb], b0, b1);
            }
        }

        // ---- row max within warp's 16 cols ----
#pragma unroll
        for (int mi = 0; mi < 2; mi++) {
            float tm0 = fmaxf(fmaxf(sc[mi][0][0], sc[mi][0][1]),
                              fmaxf(sc[mi][1][0], sc[mi][1][1]));
            float tm1 = fmaxf(fmaxf(sc[mi][0][2], sc[mi][0][3]),
                              fmaxf(sc[mi][1][2], sc[mi][1][3]));
            tm0 = fmaxf(tm0, __shfl_xor_sync(0xffffffffu, tm0, 1));
            tm0 = fmaxf(tm0, __shfl_xor_sync(0xffffffffu, tm0, 2));
            tm1 = fmaxf(tm1, __shfl_xor_sync(0xffffffffu, tm1, 1));
            tm1 = fmaxf(tm1, __shfl_xor_sync(0xffffffffu, tm1, 2));
            sm.redm[cw][rb + mi * 16 + g]     = tm0;
            sm.redm[cw][rb + mi * 16 + g + 8] = tm1;
        }
        __syncthreads();

        float alpha[2][2];
#pragma unroll
        for (int mi = 0; mi < 2; mi++)
#pragma unroll
            for (int hh = 0; hh < 2; hh++) {
                int row = rb + mi * 16 + g + hh * 8;
                float mx = fmaxf(fmaxf(sm.redm[0][row], sm.redm[1][row]),
                                 fmaxf(sm.redm[2][row], sm.redm[3][row]));
                float nm = fmaxf(m[mi][hh], mx);
                alpha[mi][hh] = __expf(m[mi][hh] - nm);
                m[mi][hh] = nm;
            }

        // ---- P = exp(S-m): write tf32 to ps, accumulate partial sums ----
#pragma unroll
        for (int mi = 0; mi < 2; mi++) {
            float ts0 = 0.f, ts1 = 0.f;
#pragma unroll
            for (int nb = 0; nb < 2; nb++) {
                float p0 = __expf(sc[mi][nb][0] - m[mi][0]);
                float p1 = __expf(sc[mi][nb][1] - m[mi][0]);
                float p2 = __expf(sc[mi][nb][2] - m[mi][1]);
                float p3 = __expf(sc[mi][nb][3] - m[mi][1]);
                ts0 += p0 + p1;
                ts1 += p2 + p3;
                int col = (cw << 4) + nb * 8 + 2 * tg;
                int row = rb + mi * 16 + g;
                *(float2*)&sm.ps[row][col] =
                    make_float2(to_tf32(p0), to_tf32(p1));
                *(float2*)&sm.ps[row + 8][col] =
                    make_float2(to_tf32(p2), to_tf32(p3));
            }
            ts0 += __shfl_xor_sync(0xffffffffu, ts0, 1);
            ts0 += __shfl_xor_sync(0xffffffffu, ts0, 2);
            ts1 += __shfl_xor_sync(0xffffffffu, ts1, 1);
            ts1 += __shfl_xor_sync(0xffffffffu, ts1, 2);
            sm.reds[cw][rb + mi * 16 + g]     = ts0;
            sm.reds[cw][rb + mi * 16 + g + 8] = ts1;
        }
        __syncthreads();

#pragma unroll
        for (int mi = 0; mi < 2; mi++)
#pragma unroll
            for (int hh = 0; hh < 2; hh++) {
                int row = rb + mi * 16 + g + hh * 8;
                float ts = (sm.reds[0][row] + sm.reds[1][row]) +
                           (sm.reds[2][row] + sm.reds[3][row]);
                l[mi][hh] = l[mi][hh] * alpha[mi][hh] + ts;
            }

        // rescale accumulators
#pragma unroll
        for (int mi = 0; mi < 2; mi++)
#pragma unroll
            for (int nb = 0; nb < 8; nb++) {
                acc[mi][nb][0] *= alpha[mi][0];
                acc[mi][nb][1] *= alpha[mi][0];
                acc[mi][nb][2] *= alpha[mi][1];
                acc[mi][nb][3] *= alpha[mi][1];
            }

        // ---- acc += P @ h_j : warp covers 32 rows x 64 channels ----
#pragma unroll
        for (int kb = 0; kb < 8; kb++) {
            float aP[2][4];
#pragma unroll
            for (int mi = 0; mi < 2; mi++) {
                int row = rb + mi * 16 + g;
                aP[mi][0] = sm.ps[row][kb * 8 + tg];
                aP[mi][1] = sm.ps[row + 8][kb * 8 + tg];
                aP[mi][2] = sm.ps[row][kb * 8 + tg + 4];
                aP[mi][3] = sm.ps[row + 8][kb * 8 + tg + 4];
            }
#pragma unroll
            for (int nb = 0; nb < 8; nb++) {
                int c0 = (cw << 6) + nb * 8 + g;
                float b0 = sm.hs[kb * 8 + tg][c0];
                float b1 = sm.hs[kb * 8 + tg + 4][c0];
#pragma unroll
                for (int mi = 0; mi < 2; mi++)
                    mma_tf32(acc[mi][nb], aP[mi], b0, b1);
            }
        }
    }

    // ---- finalize: divide by l, write o ----
#pragma unroll
    for (int mi = 0; mi < 2; mi++) {
        float inv0 = 1.0f / l[mi][0];
        float inv1 = 1.0f / l[mi][1];
        size_t row = (size_t)b * NTOK + i0 + rb + mi * 16 + g;
#pragma unroll
        for (int nb = 0; nb < 8; nb++) {
            int col = (cw << 6) + nb * 8 + 2 * tg;
            *(float2*)(g_o + row * CDIM + col) =
                make_float2(acc[mi][nb][0] * inv0, acc[mi][nb][1] * inv0);
            *(float2*)(g_o + (row + 8) * CDIM + col) =
                make_float2(acc[mi][nb][2] * inv1, acc[mi][nb][3] * inv1);
        }
    }
}

// ---------------------------------------------------------------------------
extern "C" void kernel_launch(void* const* d_in, const int* in_sizes, int n_in,
                              void* d_out, int out_size) {
    const float* x     = (const float*)d_in[0];
    const float* Wf    = (const float*)d_in[1];
    const float* Wg    = (const float*)d_in[2];
    const float* Wh    = (const float*)d_in[3];
    const float* Wv    = (const float*)d_in[4];
    const float* gamma = (const float*)d_in[5];
    float* out = (float*)d_out;

    const int M = BATCH * NTOK;  // 32768

    gemm_k<0><<<dim3(M / 64, 1), 256>>>(x, Wf, nullptr, nullptr, nullptr, M, CDIM, FDIM);
    gemm_k<1><<<dim3(M / 64, 1), 256>>>(x, Wg, nullptr, nullptr, nullptr, M, CDIM, FDIM);
    gemm_k<2><<<dim3(M / 64, 4), 256>>>(x, Wh, nullptr, nullptr, nullptr, M, CDIM, CDIM);

    static_assert(sizeof(AttnSmem) <= 120 * 1024, "smem");
    cudaFuncSetAttribute(attn_k, cudaFuncAttributeMaxDynamicSharedMemorySize,
                         (int)sizeof(AttnSmem));
    attn_k<<<dim3(NTOK / 64, BATCH), 256, sizeof(AttnSmem)>>>();

    gemm_k<3><<<dim3(M / 64, 4), 256>>>(nullptr, Wv, out, x, gamma, M, CDIM, CDIM);
}

// round 5
// speedup vs baseline: 5.3752x; 1.5312x over previous
#include <cuda_runtime.h>
#include <cstdint>

#define NTOK 4096
#define CDIM 256
#define FDIM 64
#define BATCH 8

// Scratch (allocation-free rule: __device__ globals)
__device__ float g_f[BATCH * NTOK * FDIM];   // 8 MB
__device__ float g_g[BATCH * NTOK * FDIM];   // 8 MB
__device__ float g_h[BATCH * NTOK * CDIM];   // 32 MB
__device__ float g_o[BATCH * NTOK * CDIM];   // 32 MB

// ---------------------------------------------------------------------------
// helpers
// ---------------------------------------------------------------------------
__device__ __forceinline__ float to_tf32(float x) {
    unsigned int u;
    asm("cvt.rna.tf32.f32 %0, %1;" : "=r"(u) : "f"(x));
    return __uint_as_float(u);
}

__device__ __forceinline__ void mma_tf32(float c[4], const float a[4],
                                         float b0, float b1) {
    asm volatile(
        "mma.sync.aligned.m16n8k8.row.col.f32.tf32.tf32.f32 "
        "{%0,%1,%2,%3}, {%4,%5,%6,%7}, {%8,%9}, {%0,%1,%2,%3};"
        : "+f"(c[0]), "+f"(c[1]), "+f"(c[2]), "+f"(c[3])
        : "r"(__float_as_uint(a[0])), "r"(__float_as_uint(a[1])),
          "r"(__float_as_uint(a[2])), "r"(__float_as_uint(a[3])),
          "r"(__float_as_uint(b0)), "r"(__float_as_uint(b1)));
}

__device__ __forceinline__ void cp_async16(void* sdst, const void* gsrc) {
    unsigned int saddr = (unsigned int)__cvta_generic_to_shared(sdst);
    asm volatile("cp.async.cg.shared.global [%0], [%1], 16;"
                 :: "r"(saddr), "l"(gsrc));
}
#define CP_COMMIT() asm volatile("cp.async.commit_group;")
#define CP_WAIT0()  asm volatile("cp.async.wait_group 0;")

// ---------------------------------------------------------------------------
// Generic 64x64-tile GEMM: C[M,N] = A[M,K] @ W[K,N]
// MODE 0/1/2: C = g_f / g_g / g_h.  MODE 3: A = g_o, C = out, epilogue
//             C = gamma*acc + X (residual).
// ---------------------------------------------------------------------------
template <int MODE>
__global__ __launch_bounds__(256) void gemm_k(
    const float* __restrict__ Aext, const float* __restrict__ W,
    float* __restrict__ Cext, const float* __restrict__ X,
    const float* __restrict__ gamma, int M, int K, int N)
{
    __shared__ float As[64][17];
    __shared__ float Ws[16][64];

    const float* __restrict__ A = (MODE == 3) ? g_o : Aext;
    float* __restrict__ C =
        (MODE == 0) ? g_f : (MODE == 1) ? g_g : (MODE == 2) ? g_h : Cext;

    const int m0 = blockIdx.x * 64;
    const int n0 = blockIdx.y * 64;
    const int tid = threadIdx.x;
    const int ty = tid >> 4;
    const int tx = tid & 15;

    float acc[4][4];
#pragma unroll
    for (int i = 0; i < 4; i++)
#pragma unroll
        for (int j = 0; j < 4; j++) acc[i][j] = 0.0f;

    for (int k0 = 0; k0 < K; k0 += 16) {
        {
            int r = tid >> 2;
            int q = (tid & 3) << 2;
            float4 v = *(const float4*)(A + (size_t)(m0 + r) * K + k0 + q);
            As[r][q + 0] = v.x; As[r][q + 1] = v.y;
            As[r][q + 2] = v.z; As[r][q + 3] = v.w;
        }
        {
            int kr = tid >> 4;
            int cq = (tid & 15) << 2;
            *(float4*)(&Ws[kr][cq]) =
                *(const float4*)(W + (size_t)(k0 + kr) * N + n0 + cq);
        }
        __syncthreads();
#pragma unroll
        for (int k = 0; k < 16; k++) {
            float4 b = *(const float4*)(&Ws[k][tx << 2]);
#pragma unroll
            for (int i = 0; i < 4; i++) {
                float a = As[(ty << 2) + i][k];
                acc[i][0] += a * b.x; acc[i][1] += a * b.y;
                acc[i][2] += a * b.z; acc[i][3] += a * b.w;
            }
        }
        __syncthreads();
    }

    float gam = (MODE == 3) ? *gamma : 0.0f;
#pragma unroll
    for (int i = 0; i < 4; i++) {
        size_t row = (size_t)(m0 + (ty << 2) + i);
        float4 v;
        if (MODE == 3) {
            float4 xr = *(const float4*)(X + row * N + n0 + (tx << 2));
            v.x = gam * acc[i][0] + xr.x;
            v.y = gam * acc[i][1] + xr.y;
            v.z = gam * acc[i][2] + xr.z;
            v.w = gam * acc[i][3] + xr.w;
        } else {
            v.x = acc[i][0]; v.y = acc[i][1]; v.z = acc[i][2]; v.w = acc[i][3];
        }
        *(float4*)(C + row * N + n0 + (tx << 2)) = v;
    }
}

// ---------------------------------------------------------------------------
// Flash attention with tf32 mma.sync (m16n8k8), cp.async double-buffered
// j-tiles. CTA = 256 threads = 8 warps: rw = wid&1 (row half, 32 rows),
// cw = wid>>1 (16 j-cols in S phase, 64 channels in PV phase).
// g/h stored as raw fp32 (MMA reads high bits; truncation ok for tf32).
// ---------------------------------------------------------------------------
struct AttnSmem {
    float gs[2][64][68];   // g j-tile double buf   34816 B
    float hs[2][64][264];  // h j-tile double buf  135168 B
    float ps[64][68];      // P tile (tf32)         17408 B
    float redm[4][64];     // per-cw row max         1024 B
    float reds[4][64];     // per-cw row sums        1024 B
};                          // total ~189.4 KB

__global__ __launch_bounds__(256) void attn_k() {
    extern __shared__ char sraw[];
    AttnSmem& sm = *reinterpret_cast<AttnSmem*>(sraw);

    const int tid  = threadIdx.x;
    const int wid  = tid >> 5;
    const int lane = tid & 31;
    const int g    = lane >> 2;     // 0..7
    const int tg   = lane & 3;      // 0..3
    const int rw   = wid & 1;
    const int cw   = wid >> 1;      // 0..3
    const int rb   = rw << 5;       // 0 / 32

    const int b  = blockIdx.y;
    const int i0 = blockIdx.x * 64;

    const float* __restrict__ fb = g_f + (size_t)b * NTOK * FDIM;
    const float* __restrict__ gb = g_g + (size_t)b * NTOK * FDIM;
    const float* __restrict__ hb = g_h + (size_t)b * NTOK * CDIM;

    // per-thread cp.async assignments:
    // g tile: 1024 chunks of 16B -> 4 per thread
    const int g_r  = tid >> 2;            // row 0..63
    const int g_c0 = (tid & 3) << 2;      // float col base {0,4,8,12} then +16
    // h tile: 4096 chunks -> 16 per thread
    const int h_r  = tid >> 2;            // row 0..63
    const int h_c0 = (tid & 3) << 2;      // float col base, step 16 floats

    // prefetch helper (lambda-free for nvcc friendliness)
    // issues g (4 chunks) + h (16 chunks) for tile j0 into buffer buf
#define PREFETCH_TILE(J0, BUF)                                             \
    do {                                                                   \
        const float* gsrc = gb + (size_t)((J0) + g_r) * FDIM;              \
        _Pragma("unroll")                                                  \
        for (int q = 0; q < 4; q++)                                        \
            cp_async16(&sm.gs[BUF][g_r][g_c0 + q * 16],                    \
                       gsrc + g_c0 + q * 16);                              \
        const float* hsrc = hb + (size_t)((J0) + h_r) * CDIM;              \
        _Pragma("unroll")                                                  \
        for (int q = 0; q < 16; q++)                                       \
            cp_async16(&sm.hs[BUF][h_r][h_c0 + q * 16],                    \
                       hsrc + h_c0 + q * 16);                              \
        CP_COMMIT();                                                       \
    } while (0)

    // persistent A fragments of f (tf32), 2 m16 blocks x 8 k-blocks
    float aS[2][8][4];
#pragma unroll
    for (int mi = 0; mi < 2; mi++) {
        int row0 = i0 + rb + mi * 16 + g;
#pragma unroll
        for (int kb = 0; kb < 8; kb++) {
            int k0 = kb * 8 + tg;
            aS[mi][kb][0] = to_tf32(fb[(size_t)row0 * FDIM + k0]);
            aS[mi][kb][1] = to_tf32(fb[(size_t)(row0 + 8) * FDIM + k0]);
            aS[mi][kb][2] = to_tf32(fb[(size_t)row0 * FDIM + k0 + 4]);
            aS[mi][kb][3] = to_tf32(fb[(size_t)(row0 + 8) * FDIM + k0 + 4]);
        }
    }

    float acc[2][8][4];
#pragma unroll
    for (int mi = 0; mi < 2; mi++)
#pragma unroll
        for (int nb = 0; nb < 8; nb++)
#pragma unroll
            for (int q = 0; q < 4; q++) acc[mi][nb][q] = 0.0f;

    float m[2][2] = {{-1e30f, -1e30f}, {-1e30f, -1e30f}};
    float l[2][2] = {{0.f, 0.f}, {0.f, 0.f}};

    // preload tile 0 into buffer 0
    PREFETCH_TILE(0, 0);

    for (int t = 0; t < NTOK / 64; t++) {
        const int buf = t & 1;

        CP_WAIT0();
        __syncthreads();  // buf data visible; all warps done with buf^1 reads

        if (t + 1 < NTOK / 64) {
            PREFETCH_TILE((t + 1) * 64, buf ^ 1);
        }

        // ---- S = f_i @ g_j^T : warp covers 32 rows x 16 j-cols ----
        float sc[2][2][4];
#pragma unroll
        for (int mi = 0; mi < 2; mi++)
#pragma unroll
            for (int nb = 0; nb < 2; nb++)
#pragma unroll
                for (int q = 0; q < 4; q++) sc[mi][nb][q] = 0.f;

#pragma unroll
        for (int kb = 0; kb < 8; kb++) {
#pragma unroll
            for (int nb = 0; nb < 2; nb++) {
                int jn = (cw << 4) + nb * 8 + g;
                float b0 = sm.gs[buf][jn][kb * 8 + tg];
                float b1 = sm.gs[buf][jn][kb * 8 + tg + 4];
#pragma unroll
                for (int mi = 0; mi < 2; mi++)
                    mma_tf32(sc[mi][nb], aS[mi][kb], b0, b1);
            }
        }

        // ---- row max within warp's 16 cols ----
#pragma unroll
        for (int mi = 0; mi < 2; mi++) {
            float tm0 = fmaxf(fmaxf(sc[mi][0][0], sc[mi][0][1]),
                              fmaxf(sc[mi][1][0], sc[mi][1][1]));
            float tm1 = fmaxf(fmaxf(sc[mi][0][2], sc[mi][0][3]),
                              fmaxf(sc[mi][1][2], sc[mi][1][3]));
            tm0 = fmaxf(tm0, __shfl_xor_sync(0xffffffffu, tm0, 1));
            tm0 = fmaxf(tm0, __shfl_xor_sync(0xffffffffu, tm0, 2));
            tm1 = fmaxf(tm1, __shfl_xor_sync(0xffffffffu, tm1, 1));
            tm1 = fmaxf(tm1, __shfl_xor_sync(0xffffffffu, tm1, 2));
            sm.redm[cw][rb + mi * 16 + g]     = tm0;
            sm.redm[cw][rb + mi * 16 + g + 8] = tm1;
        }
        __syncthreads();

        float alpha[2][2];
#pragma unroll
        for (int mi = 0; mi < 2; mi++)
#pragma unroll
            for (int hh = 0; hh < 2; hh++) {
                int row = rb + mi * 16 + g + hh * 8;
                float mx = fmaxf(fmaxf(sm.redm[0][row], sm.redm[1][row]),
                                 fmaxf(sm.redm[2][row], sm.redm[3][row]));
                float nm = fmaxf(m[mi][hh], mx);
                alpha[mi][hh] = __expf(m[mi][hh] - nm);
                m[mi][hh] = nm;
            }

        // ---- P = exp(S-m): write tf32 to ps, accumulate partial sums ----
#pragma unroll
        for (int mi = 0; mi < 2; mi++) {
            float ts0 = 0.f, ts1 = 0.f;
#pragma unroll
            for (int nb = 0; nb < 2; nb++) {
                float p0 = __expf(sc[mi][nb][0] - m[mi][0]);
                float p1 = __expf(sc[mi][nb][1] - m[mi][0]);
                float p2 = __expf(sc[mi][nb][2] - m[mi][1]);
                float p3 = __expf(sc[mi][nb][3] - m[mi][1]);
                ts0 += p0 + p1;
                ts1 += p2 + p3;
                int col = (cw << 4) + nb * 8 + 2 * tg;
                int row = rb + mi * 16 + g;
                *(float2*)&sm.ps[row][col] =
                    make_float2(to_tf32(p0), to_tf32(p1));
                *(float2*)&sm.ps[row + 8][col] =
                    make_float2(to_tf32(p2), to_tf32(p3));
            }
            ts0 += __shfl_xor_sync(0xffffffffu, ts0, 1);
            ts0 += __shfl_xor_sync(0xffffffffu, ts0, 2);
            ts1 += __shfl_xor_sync(0xffffffffu, ts1, 1);
            ts1 += __shfl_xor_sync(0xffffffffu, ts1, 2);
            sm.reds[cw][rb + mi * 16 + g]     = ts0;
            sm.reds[cw][rb + mi * 16 + g + 8] = ts1;
        }
        __syncthreads();

#pragma unroll
        for (int mi = 0; mi < 2; mi++)
#pragma unroll
            for (int hh = 0; hh < 2; hh++) {
                int row = rb + mi * 16 + g + hh * 8;
                float ts = (sm.reds[0][row] + sm.reds[1][row]) +
                           (sm.reds[2][row] + sm.reds[3][row]);
                l[mi][hh] = l[mi][hh] * alpha[mi][hh] + ts;
            }

        // rescale accumulators
#pragma unroll
        for (int mi = 0; mi < 2; mi++)
#pragma unroll
            for (int nb = 0; nb < 8; nb++) {
                acc[mi][nb][0] *= alpha[mi][0];
                acc[mi][nb][1] *= alpha[mi][0];
                acc[mi][nb][2] *= alpha[mi][1];
                acc[mi][nb][3] *= alpha[mi][1];
            }

        // ---- acc += P @ h_j : warp covers 32 rows x 64 channels ----
#pragma unroll
        for (int kb = 0; kb < 8; kb++) {
            float aP[2][4];
#pragma unroll
            for (int mi = 0; mi < 2; mi++) {
                int row = rb + mi * 16 + g;
                aP[mi][0] = sm.ps[row][kb * 8 + tg];
                aP[mi][1] = sm.ps[row + 8][kb * 8 + tg];
                aP[mi][2] = sm.ps[row][kb * 8 + tg + 4];
                aP[mi][3] = sm.ps[row + 8][kb * 8 + tg + 4];
            }
#pragma unroll
            for (int nb = 0; nb < 8; nb++) {
                int c0 = (cw << 6) + nb * 8 + g;
                float b0 = sm.hs[buf][kb * 8 + tg][c0];
                float b1 = sm.hs[buf][kb * 8 + tg + 4][c0];
#pragma unroll
                for (int mi = 0; mi < 2; mi++)
                    mma_tf32(acc[mi][nb], aP[mi], b0, b1);
            }
        }
    }

    // ---- finalize: divide by l, write o ----
#pragma unroll
    for (int mi = 0; mi < 2; mi++) {
        float inv0 = 1.0f / l[mi][0];
        float inv1 = 1.0f / l[mi][1];
        size_t row = (size_t)b * NTOK + i0 + rb + mi * 16 + g;
#pragma unroll
        for (int nb = 0; nb < 8; nb++) {
            int col = (cw << 6) + nb * 8 + 2 * tg;
            *(float2*)(g_o + row * CDIM + col) =
                make_float2(acc[mi][nb][0] * inv0, acc[mi][nb][1] * inv0);
            *(float2*)(g_o + (row + 8) * CDIM + col) =
                make_float2(acc[mi][nb][2] * inv1, acc[mi][nb][3] * inv1);
        }
    }
#undef PREFETCH_TILE
}

// ---------------------------------------------------------------------------
extern "C" void kernel_launch(void* const* d_in, const int* in_sizes, int n_in,
                              void* d_out, int out_size) {
    const float* x     = (const float*)d_in[0];
    const float* Wf    = (const float*)d_in[1];
    const float* Wg    = (const float*)d_in[2];
    const float* Wh    = (const float*)d_in[3];
    const float* Wv    = (const float*)d_in[4];
    const float* gamma = (const float*)d_in[5];
    float* out = (float*)d_out;

    const int M = BATCH * NTOK;  // 32768

    gemm_k<0><<<dim3(M / 64, 1), 256>>>(x, Wf, nullptr, nullptr, nullptr, M, CDIM, FDIM);
    gemm_k<1><<<dim3(M / 64, 1), 256>>>(x, Wg, nullptr, nullptr, nullptr, M, CDIM, FDIM);
    gemm_k<2><<<dim3(M / 64, 4), 256>>>(x, Wh, nullptr, nullptr, nullptr, M, CDIM, CDIM);

    static_assert(sizeof(AttnSmem) <= 220 * 1024, "smem");
    cudaFuncSetAttribute(attn_k, cudaFuncAttributeMaxDynamicSharedMemorySize,
                         (int)sizeof(AttnSmem));
    attn_k<<<dim3(NTOK / 64, BATCH), 256, sizeof(AttnSmem)>>>();

    gemm_k<3><<<dim3(M / 64, 4), 256>>>(nullptr, Wv, out, x, gamma, M, CDIM, CDIM);
}